// round 10
// baseline (speedup 1.0000x reference)
#include <cuda_runtime.h>
#include <cuda_bf16.h>
#include <cstdint>

#define NB   8            // b's per block
#define TPB  128          // 16 threads per b, 4 candidates per thread
#define EPS  1e-6f
typedef unsigned long long ull;

// dynamic smem layout (floats):
//   sRp   : [0, NB*576)            18432 B (R_pred slice, candidate-major)
//   sgsym : [+NB*576, +NB*240)      7680 B (Gsym duplicated pairs, 80B per (b,s))
//   sgt   : [+..., +NB*9)            288 B
#define OFF_RP    0
#define OFF_GSYM  (NB * 576)
#define OFF_GT    (OFF_GSYM + NB * 240)
#define SMEM_FLOATS (OFF_GT + NB * 9)
#define SMEM_BYTES  (SMEM_FLOATS * 4)

__device__ float g_partial[8192];
__device__ unsigned int g_count = 0;    // self-resets via atomicInc wrap

__global__ __launch_bounds__(TPB, 8)
void geo_fused(const float* __restrict__ R_pred,
               const float* __restrict__ R_gt,
               const float* __restrict__ rot,
               float* __restrict__ out,
               int B, int grid, float invB)
{
    extern __shared__ float smem[];
    float* sRp   = smem + OFF_RP;
    float* sgsym = smem + OFF_GSYM;
    float* sgt   = smem + OFF_GT;

    __shared__ float ssum;
    __shared__ int slast;

    const int tid = threadIdx.x;
    const int b0  = blockIdx.x * NB;
    const int nb  = min(NB, B - b0);
    const int n4  = nb * 144;

    // ---- 1) async coalesced staging of R_pred slice (9 x 16B per thread) ----
    {
        const float4* src = reinterpret_cast<const float4*>(R_pred + (size_t)b0 * 576) + tid;
        uint32_t daddr = (uint32_t)__cvta_generic_to_shared(sRp) + tid * 16u;
        #pragma unroll
        for (int j = 0; j < 9; j++) {
            if (tid + j * TPB < n4)
                asm volatile("cp.async.cg.shared.global [%0], [%1], 16;"
                             :: "r"(daddr + j * (TPB * 16u)), "l"(src + j * TPB) : "memory");
        }
        asm volatile("cp.async.commit_group;" ::: "memory");
    }

    // ---- 2) R_gt slice to smem; sync so Gsym phase can read it ----
    if (tid < nb * 9) sgt[tid] = __ldg(R_gt + (size_t)b0 * 9 + tid);
    if (tid == 0) ssum = 0.0f;
    __syncthreads();

    // ---- 3) Gsym[b,s,i,k] = sum_j rot[s,i,j]*R_gt[b,j,k]; duplicated pairs.
    //      One (s,e) per thread (indices computed ONCE), loop over b's.
    //      Overlaps with the in-flight cp.async.
    if (tid < 108) {
        const int s  = tid / 9;
        const int e  = tid - s * 9;
        const int ii = e / 3;
        const int kk = e - ii * 3;
        const float r0 = __ldg(rot + s * 9 + ii * 3 + 0);
        const float r1 = __ldg(rot + s * 9 + ii * 3 + 1);
        const float r2 = __ldg(rot + s * 9 + ii * 3 + 2);
        float* dst = sgsym + s * 20 + e * 2;
        const float* gt = sgt + kk;
        #pragma unroll
        for (int bl = 0; bl < NB; bl++) {
            float v = fmaf(r2, gt[bl * 9 + 6],
                      fmaf(r1, gt[bl * 9 + 3],
                           r0 * gt[bl * 9 + 0]));
            float2 d; d.x = v; d.y = v;
            *reinterpret_cast<float2*>(dst + bl * 240) = d;
        }
    }

    asm volatile("cp.async.wait_group 0;" ::: "memory");
    __syncthreads();

    // ---- 4) main compute: 4 candidates per thread, no per-thread M phase ----
    const int bl = tid >> 4;
    const int m  = tid & 15;
    float cmax = -1e30f;

    {
        // 4 candidates = 9 conflict-free LDS.128; pack pairs (c0,c1),(c2,c3)
        ull a[9], bq[9];
        const float4* p4 = reinterpret_cast<const float4*>(&sRp[(bl * 64 + m * 4) * 9]);
        {
            float rp[36];
            #pragma unroll
            for (int k = 0; k < 9; k++) {
                float4 v = p4[k];
                rp[4*k+0] = v.x; rp[4*k+1] = v.y; rp[4*k+2] = v.z; rp[4*k+3] = v.w;
            }
            #pragma unroll
            for (int e = 0; e < 9; e++) {
                asm("mov.b64 %0, {%1, %2};" : "=l"(a[e])  : "f"(rp[e]),      "f"(rp[9  + e]));
                asm("mov.b64 %0, {%1, %2};" : "=l"(bq[e]) : "f"(rp[18 + e]), "f"(rp[27 + e]));
            }
        }

        // s-loop: tr[c,s] = <Gsym[bl,s], Rp[c]> via duplicated-pair f32x2
        const float* gb = sgsym + bl * 240;
        #pragma unroll
        for (int s = 0; s < 12; s++) {
            const ull* gp = reinterpret_cast<const ull*>(gb + s * 20);
            ull acc0 = 0ull, acc1 = 0ull;
            #pragma unroll
            for (int h = 0; h < 4; h++) {           // broadcast LDS.128
                ulonglong2 q = reinterpret_cast<const ulonglong2*>(gp)[h];
                asm("fma.rn.f32x2 %0, %1, %2, %3;" : "=l"(acc0) : "l"(a[2*h]),    "l"(q.x), "l"(acc0));
                asm("fma.rn.f32x2 %0, %1, %2, %3;" : "=l"(acc1) : "l"(bq[2*h]),   "l"(q.x), "l"(acc1));
                asm("fma.rn.f32x2 %0, %1, %2, %3;" : "=l"(acc0) : "l"(a[2*h+1]),  "l"(q.y), "l"(acc0));
                asm("fma.rn.f32x2 %0, %1, %2, %3;" : "=l"(acc1) : "l"(bq[2*h+1]), "l"(q.y), "l"(acc1));
            }
            ull g8 = gp[8];
            asm("fma.rn.f32x2 %0, %1, %2, %3;" : "=l"(acc0) : "l"(a[8]),  "l"(g8), "l"(acc0));
            asm("fma.rn.f32x2 %0, %1, %2, %3;" : "=l"(acc1) : "l"(bq[8]), "l"(g8), "l"(acc1));

            float2 f0 = *reinterpret_cast<float2*>(&acc0);
            float2 f1 = *reinterpret_cast<float2*>(&acc1);
            cmax = fmaxf(cmax, fmaxf(fmaxf(f0.x, f0.y), fmaxf(f1.x, f1.y)));
        }
    }

    // max over the 16 lanes sharing this b
    #pragma unroll
    for (int w = 8; w >= 1; w >>= 1)
        cmax = fmaxf(cmax, __shfl_xor_sync(0xFFFFFFFFu, cmax, w));

    if (m == 0 && bl < nb) {
        float cosv = (cmax - 1.0f) * 0.5f;
        cosv = fminf(fmaxf(cosv, -1.0f + EPS), 1.0f - EPS);
        atomicAdd(&ssum, acosf(cosv));      // 8 shared atomics per block
    }
    __syncthreads();

    // ---- 5) publish partial; last block reduces (counter wraps to 0) ----
    if (tid == 0) {
        g_partial[blockIdx.x] = ssum;
        __threadfence();
        unsigned int old = atomicInc(&g_count, (unsigned int)(grid - 1));
        slast = (old == (unsigned int)(grid - 1));
    }
    __syncthreads();

    if (slast) {
        __shared__ float warpsum[TPB / 32];
        float v = 0.0f;
        for (int i = tid; i < grid; i += TPB) v += __ldcg(&g_partial[i]);
        #pragma unroll
        for (int w = 16; w >= 1; w >>= 1)
            v += __shfl_xor_sync(0xFFFFFFFFu, v, w);
        if ((tid & 31) == 0) warpsum[tid >> 5] = v;
        __syncthreads();
        if (tid < TPB / 32) {
            float w2 = warpsum[tid];
            #pragma unroll
            for (int w = TPB / 64; w >= 1; w >>= 1)
                w2 += __shfl_xor_sync(0xFFu, w2, w);
            if (tid == 0) out[0] = w2 * invB;
        }
    }
}

extern "C" void kernel_launch(void* const* d_in, const int* in_sizes, int n_in,
                              void* d_out, int out_size)
{
    const float* R_pred = (const float*)d_in[0];
    const float* R_gt   = (const float*)d_in[1];
    const float* rot    = (const float*)d_in[2];
    float* out = (float*)d_out;

    const int B = in_sizes[1] / 9;
    const int grid = (B + NB - 1) / NB;

    cudaFuncSetAttribute(geo_fused, cudaFuncAttributeMaxDynamicSharedMemorySize, SMEM_BYTES);
    geo_fused<<<grid, TPB, SMEM_BYTES>>>(R_pred, R_gt, rot, out, B, grid, 1.0f / (float)B);
}